// round 1
// baseline (speedup 1.0000x reference)
#include <cuda_runtime.h>
#include <math.h>

#define B 8
#define S 1024
#define INDIM 512
#define H 512
#define NH 8
#define HD 64
#define BS (B*S)

// ---------------- scratch (static __device__; no allocations) ----------------
__device__ float g_h[BS*H];
__device__ float g_qkv[BS*3*H];
__device__ float g_ctx[BS*H];
__device__ float g_tmp[BS*H];
__device__ float g_hatt[BS*H];
__device__ float g_prex[BS*H];
__device__ float g_outs[BS*H];
__device__ float g_W2T[H*H];
__device__ float g_Wc[3*H*H];
__device__ float g_bc[3*H];
__device__ float g_z[B*H];
__device__ unsigned g_bar;

__global__ void init_kernel() { g_bar = 0u; }

// ---------------- generic fp32 GEMM: C[M,N] = A[M,K] * W[N,K]^T + bias ----------------
__global__ __launch_bounds__(256) void gemm_tn(
    const float* __restrict__ A, int lda,
    const float* __restrict__ W, int ldw,
    const float* __restrict__ bias,
    float* __restrict__ C,
    int M, int N, int K)
{
    __shared__ float As[16][64];
    __shared__ float Ws[16][64];
    int tid = threadIdx.x;
    int tx = tid & 15, ty = tid >> 4;
    int bm = blockIdx.y * 64, bn = blockIdx.x * 64;
    int lr = tid >> 2;
    int lk = (tid & 3) << 2;
    const float* Ap = A + (size_t)(bm + lr) * lda + lk;
    const float* Wp = W + (size_t)(bn + lr) * ldw + lk;
    float acc[4][4];
#pragma unroll
    for (int i = 0; i < 4; i++)
#pragma unroll
        for (int j = 0; j < 4; j++) acc[i][j] = 0.f;

    for (int k0 = 0; k0 < K; k0 += 16) {
        float4 av = *(const float4*)(Ap + k0);
        float4 wv = *(const float4*)(Wp + k0);
        __syncthreads();
        As[lk + 0][lr] = av.x; As[lk + 1][lr] = av.y; As[lk + 2][lr] = av.z; As[lk + 3][lr] = av.w;
        Ws[lk + 0][lr] = wv.x; Ws[lk + 1][lr] = wv.y; Ws[lk + 2][lr] = wv.z; Ws[lk + 3][lr] = wv.w;
        __syncthreads();
#pragma unroll
        for (int kk = 0; kk < 16; kk++) {
            float4 a = *(const float4*)&As[kk][ty << 2];
            float4 w = *(const float4*)&Ws[kk][tx << 2];
            float ar[4] = {a.x, a.y, a.z, a.w};
            float wr[4] = {w.x, w.y, w.z, w.w};
#pragma unroll
            for (int i = 0; i < 4; i++)
#pragma unroll
                for (int j = 0; j < 4; j++)
                    acc[i][j] += ar[i] * wr[j];
        }
    }
#pragma unroll
    for (int j = 0; j < 4; j++) {
        int n = bn + (tx << 2) + j;
        float bv = bias ? bias[n] : 0.f;
#pragma unroll
        for (int i = 0; i < 4; i++) {
            int m = bm + (ty << 2) + i;
            C[(size_t)m * N + n] = acc[i][j] + bv;
        }
    }
}

// ---------------- flash attention (fp32, no mask) ----------------
__global__ __launch_bounds__(128) void attn_kernel(const float* __restrict__ qkv,
                                                   float* __restrict__ ctx)
{
    __shared__ float Ks[64][64];
    __shared__ float Vs[64][64];
    int qt = blockIdx.x;          // q tile (16)
    int bh = blockIdx.y;          // b*NH+h (64)
    int b = bh >> 3, h = bh & 7;
    const float* base = qkv + (size_t)b * S * 1536;
    int tid = threadIdx.x;
    int r = tid >> 1, half = tid & 1;   // 2 threads per q-row, split over HD
    int qrow = qt * 64 + r;

    float q[32];
    {
        const float* qp = base + (size_t)qrow * 1536 + h * 64 + half * 32;
#pragma unroll
        for (int i = 0; i < 32; i++) q[i] = qp[i] * 0.125f;   // 1/sqrt(64)
    }
    float m = -1e30f, l = 0.f;
    float acc[32];
#pragma unroll
    for (int i = 0; i < 32; i++) acc[i] = 0.f;

    for (int kt = 0; kt < 16; kt++) {
        __syncthreads();
#pragma unroll
        for (int ii = 0; ii < 8; ii++) {
            int fi = tid + 128 * ii;          // 0..1023 float4s
            int row = fi >> 4;
            int d4 = (fi & 15) << 2;
            const float* kp = base + (size_t)(kt * 64 + row) * 1536 + 512 + h * 64 + d4;
            *(float4*)&Ks[row][d4] = *(const float4*)kp;
            *(float4*)&Vs[row][d4] = *(const float4*)(kp + 512);
        }
        __syncthreads();

        float s[64];
#pragma unroll
        for (int j = 0; j < 64; j++) {
            float a = 0.f;
#pragma unroll
            for (int i = 0; i < 32; i += 4) {
                float4 kk = *(const float4*)&Ks[j][half * 32 + i];
                a += q[i] * kk.x + q[i + 1] * kk.y + q[i + 2] * kk.z + q[i + 3] * kk.w;
            }
            s[j] = a;
        }
#pragma unroll
        for (int j = 0; j < 64; j++) s[j] += __shfl_xor_sync(0xffffffffu, s[j], 1);

        float mx = s[0];
#pragma unroll
        for (int j = 1; j < 64; j++) mx = fmaxf(mx, s[j]);
        float mnew = fmaxf(m, mx);
        float corr = expf(m - mnew);
        l *= corr;
#pragma unroll
        for (int i = 0; i < 32; i++) acc[i] *= corr;
        float ls = 0.f;
#pragma unroll
        for (int j = 0; j < 64; j++) { float p = expf(s[j] - mnew); s[j] = p; ls += p; }
        l += ls;
        m = mnew;
#pragma unroll
        for (int j = 0; j < 64; j++) {
#pragma unroll
            for (int i = 0; i < 32; i += 4) {
                float4 vv = *(const float4*)&Vs[j][half * 32 + i];
                acc[i]     += s[j] * vv.x;
                acc[i + 1] += s[j] * vv.y;
                acc[i + 2] += s[j] * vv.z;
                acc[i + 3] += s[j] * vv.w;
            }
        }
    }
    float inv = 1.f / l;
    float* op = ctx + ((size_t)b * S + qrow) * 512 + h * 64 + half * 32;
#pragma unroll
    for (int i = 0; i < 32; i++) op[i] = acc[i] * inv;
}

// ---------------- fused residual + LayerNorm ----------------
__global__ __launch_bounds__(128) void ln_kernel(
    const float* __restrict__ A, const float* __restrict__ Bres,
    const float* __restrict__ gma, const float* __restrict__ bta,
    float* __restrict__ out)
{
    int row = blockIdx.x, tid = threadIdx.x;
    const float4* a4 = (const float4*)(A + (size_t)row * 512);
    const float4* b4 = (const float4*)(Bres + (size_t)row * 512);
    float4 x = a4[tid], y = b4[tid];
    float4 v = make_float4(x.x + y.x, x.y + y.y, x.z + y.z, x.w + y.w);
    float s = v.x + v.y + v.z + v.w;
    float q = v.x * v.x + v.y * v.y + v.z * v.z + v.w * v.w;
#pragma unroll
    for (int o = 16; o > 0; o >>= 1) {
        s += __shfl_down_sync(0xffffffffu, s, o);
        q += __shfl_down_sync(0xffffffffu, q, o);
    }
    __shared__ float rs[4], rq[4];
    int wid = tid >> 5;
    if ((tid & 31) == 0) { rs[wid] = s; rq[wid] = q; }
    __syncthreads();
    float ts = rs[0] + rs[1] + rs[2] + rs[3];
    float tq = rq[0] + rq[1] + rq[2] + rq[3];
    float mean = ts * (1.f / 512.f);
    float var = tq * (1.f / 512.f) - mean * mean;
    float rstd = rsqrtf(var + 1e-5f);
    float4 gg = ((const float4*)gma)[tid];
    float4 bb = ((const float4*)bta)[tid];
    float4 o;
    o.x = (v.x - mean) * rstd * gg.x + bb.x;
    o.y = (v.y - mean) * rstd * gg.y + bb.y;
    o.z = (v.z - mean) * rstd * gg.z + bb.z;
    o.w = (v.w - mean) * rstd * gg.w + bb.w;
    ((float4*)(out + (size_t)row * 512))[tid] = o;
}

// ---------------- 512x512 transpose (for Wc = Wfgh @ W2 via gemm_tn) ----------------
__global__ void transpose_kernel(const float* __restrict__ in, float* __restrict__ out)
{
    __shared__ float tile[32][33];
    int bx = blockIdx.x * 32, by = blockIdx.y * 32;
    int tx = threadIdx.x, ty = threadIdx.y;  // (32, 8)
    for (int i = 0; i < 32; i += 8)
        tile[ty + i][tx] = in[(size_t)(by + ty + i) * 512 + bx + tx];
    __syncthreads();
    for (int i = 0; i < 32; i += 8)
        out[(size_t)(bx + ty + i) * 512 + by + tx] = tile[tx][ty + i];
}

// ---------------- bc = Wfgh @ b2 + b_fgh ----------------
__global__ void bc_kernel(const float* __restrict__ tw, const float* __restrict__ gw,
                          const float* __restrict__ hw, const float* __restrict__ tb,
                          const float* __restrict__ gb, const float* __restrict__ hb,
                          const float* __restrict__ b2)
{
    int i = blockIdx.x * blockDim.x + threadIdx.x;
    if (i >= 1536) return;
    int part = i >> 9, r = i & 511;
    const float* Wr; float bv;
    if (part == 0)      { Wr = tw + (size_t)r * 512; bv = tb[r]; }
    else if (part == 1) { Wr = gw + (size_t)r * 512; bv = gb[r]; }
    else                { Wr = hw + (size_t)r * 512; bv = hb[r]; }
    float s = bv;
    for (int j = 0; j < 512; j++) s += Wr[j] * b2[j];
    g_bc[i] = s;
}

// ---------------- persistent LTC scan ----------------
#define NBLK 128

__device__ __forceinline__ void gridbar(unsigned target)
{
    __syncthreads();
    if (threadIdx.x == 0) {
        __threadfence();
        atomicAdd(&g_bar, 1u);
        while (*(volatile unsigned*)&g_bar < target) { }
        __threadfence();
    }
    __syncthreads();
}

__global__ __launch_bounds__(256) void scan_kernel(const float* __restrict__ ltc_w1)
{
    __shared__ float sW1[4][516];    // 4 z-columns of W1h (state half of ltc_w1)
    __shared__ float sWc[12][516];   // 12 fgh rows of merged Wc
    __shared__ float sbc[12];
    int blk = blockIdx.x, tid = threadIdx.x;

    for (int r = 0; r < 4; r++)
        for (int k = tid; k < 512; k += 256)
            sW1[r][k] = ltc_w1[(size_t)(4 * blk + r) * 1024 + 512 + k];
    for (int r = 0; r < 12; r++) {
        int row = (r >> 2) * 512 + 4 * blk + (r & 3);
        for (int k = tid; k < 512; k += 256)
            sWc[r][k] = g_Wc[(size_t)row * 512 + k];
    }
    if (tid < 12) sbc[tid] = g_bc[(tid >> 2) * 512 + 4 * blk + (tid & 3)];
    __syncthreads();

    int w = tid >> 5, lane = tid & 31;   // warp = batch
    int cl = lane >> 3, kc = lane & 7;   // stage1: 4 cols x 8 k-chunks
    int half = lane >> 4, rr = lane & 15;// stage2: 2 k-halves x 12 rows
    unsigned nb = 0;

    for (int t = 0; t < S; t++) {
        // ---- stage 1: z = tanh(prex[t] + state @ W1h^T) ----
        float acc = 0.f;
        if (t > 0) {
            const float* st = g_outs + ((size_t)w * S + (t - 1)) * H + kc * 64;
            const float* wp = sW1[cl] + kc * 64;
#pragma unroll
            for (int i = 0; i < 16; i++) {
                float4 s4 = __ldcg((const float4*)(st + i * 4));
                float4 w4 = *(const float4*)(wp + i * 4);
                acc += s4.x * w4.x + s4.y * w4.y + s4.z * w4.z + s4.w * w4.w;
            }
        }
        acc += __shfl_down_sync(0xffffffffu, acc, 4);
        acc += __shfl_down_sync(0xffffffffu, acc, 2);
        acc += __shfl_down_sync(0xffffffffu, acc, 1);
        if (kc == 0) {
            int c = 4 * blk + cl;
            float z = tanhf(g_prex[((size_t)w * S + t) * H + c] + acc);
            g_z[w * H + c] = z;
        }
        gridbar(++nb * NBLK);

        // ---- stage 2: fgh = z @ Wc^T + bc ; state update ----
        float a2 = 0.f;
        if (rr < 12) {
            const float* zp = g_z + w * H + half * 256;
            const float* wp = sWc[rr] + half * 256;
#pragma unroll
            for (int i = 0; i < 64; i++) {
                float4 z4 = __ldcg((const float4*)(zp + i * 4));
                float4 w4 = *(const float4*)(wp + i * 4);
                a2 += z4.x * w4.x + z4.y * w4.y + z4.z * w4.z + z4.w * w4.w;
            }
        }
        a2 += __shfl_down_sync(0xffffffffu, a2, 16);
        if (lane < 12) a2 += sbc[lane];
        float fv = __shfl_sync(0xffffffffu, a2, lane & 3);
        float gv = __shfl_sync(0xffffffffu, a2, 4 + (lane & 3));
        float hv = __shfl_sync(0xffffffffu, a2, 8 + (lane & 3));
        if (lane < 4) {
            int j = 4 * blk + lane;
            float ft = 1.f / (1.f + expf(-fv));            // sigmoid(f)
            float gate = 1.f / (1.f + expf(ft * (float)t)); // sigmoid(-ft * t)
            float sv = gate * gv + (1.f - gate) * hv;
            g_outs[((size_t)w * S + t) * H + j] = sv;
        }
        gridbar(++nb * NBLK);
    }
}

// ---------------- host launch ----------------
extern "C" void kernel_launch(void* const* d_in, const int* in_sizes, int n_in,
                              void* d_out, int out_size)
{
    const float* x    = (const float*)d_in[0];
    const float* ipw  = (const float*)d_in[1];
    const float* ipb  = (const float*)d_in[2];
    const float* qkvw = (const float*)d_in[3];
    const float* qkvb = (const float*)d_in[4];
    const float* aow  = (const float*)d_in[5];
    const float* aob  = (const float*)d_in[6];
    const float* w1   = (const float*)d_in[7];
    const float* b1   = (const float*)d_in[8];
    const float* w2   = (const float*)d_in[9];
    const float* b2   = (const float*)d_in[10];
    const float* tw   = (const float*)d_in[11];
    const float* tb   = (const float*)d_in[12];
    const float* gw   = (const float*)d_in[13];
    const float* gb   = (const float*)d_in[14];
    const float* hw   = (const float*)d_in[15];
    const float* hb   = (const float*)d_in[16];
    const float* n1g  = (const float*)d_in[17];
    const float* n1b  = (const float*)d_in[18];
    const float* n2g  = (const float*)d_in[19];
    const float* n2b  = (const float*)d_in[20];
    const float* ow   = (const float*)d_in[21];
    const float* ob   = (const float*)d_in[22];
    float* out = (float*)d_out;

    float *ph, *pqkv, *pctx, *ptmp, *phatt, *pprex, *pouts, *pW2T, *pWc;
    cudaGetSymbolAddress((void**)&ph,    g_h);
    cudaGetSymbolAddress((void**)&pqkv,  g_qkv);
    cudaGetSymbolAddress((void**)&pctx,  g_ctx);
    cudaGetSymbolAddress((void**)&ptmp,  g_tmp);
    cudaGetSymbolAddress((void**)&phatt, g_hatt);
    cudaGetSymbolAddress((void**)&pprex, g_prex);
    cudaGetSymbolAddress((void**)&pouts, g_outs);
    cudaGetSymbolAddress((void**)&pW2T,  g_W2T);
    cudaGetSymbolAddress((void**)&pWc,   g_Wc);

    init_kernel<<<1, 1>>>();

    // h = x @ in_proj_w^T + b
    gemm_tn<<<dim3(8, 128), 256>>>(x, 512, ipw, 512, ipb, ph, 8192, 512, 512);
    // qkv = h @ qkv_w^T + b
    gemm_tn<<<dim3(24, 128), 256>>>(ph, 512, qkvw, 512, qkvb, pqkv, 8192, 1536, 512);
    // attention
    attn_kernel<<<dim3(16, 64), 128>>>(pqkv, pctx);
    // attn out proj
    gemm_tn<<<dim3(8, 128), 256>>>(pctx, 512, aow, 512, aob, ptmp, 8192, 512, 512);
    // h_att = LN(h + attn_out)
    ln_kernel<<<8192, 128>>>(ph, ptmp, n1g, n1b, phatt);
    // prex = h_att @ W1x^T + b1  (x-half of ltc_w1, ldw = 1024)
    gemm_tn<<<dim3(8, 128), 256>>>(phatt, 512, w1, 1024, b1, pprex, 8192, 512, 512);
    // W2T, then Wc = [tw;gw;hw] @ W2   (as A @ (W2^T)^T)
    transpose_kernel<<<dim3(16, 16), dim3(32, 8)>>>(w2, pW2T);
    gemm_tn<<<dim3(8, 8), 256>>>(tw, 512, pW2T, 512, nullptr, pWc,            512, 512, 512);
    gemm_tn<<<dim3(8, 8), 256>>>(gw, 512, pW2T, 512, nullptr, pWc + 262144,   512, 512, 512);
    gemm_tn<<<dim3(8, 8), 256>>>(hw, 512, pW2T, 512, nullptr, pWc + 524288,   512, 512, 512);
    bc_kernel<<<6, 256>>>(tw, gw, hw, tb, gb, hb, b2);
    // persistent scan
    scan_kernel<<<NBLK, 256>>>(w1);
    // LN2 + out proj
    ln_kernel<<<8192, 128>>>(pouts, phatt, n2g, n2b, ptmp);
    gemm_tn<<<dim3(8, 128), 256>>>(ptmp, 512, ow, 512, ob, out, 8192, 512, 512);
}

// round 2
// speedup vs baseline: 2.0189x; 2.0189x over previous
#include <cuda_runtime.h>
#include <math.h>

#define B 8
#define S 1024
#define INDIM 512
#define H 512
#define NH 8
#define HD 64
#define BS (B*S)

// ---------------- scratch (static __device__; no allocations) ----------------
__device__ float g_h[BS*H];
__device__ float g_qkv[BS*3*H];
__device__ float g_ctx[BS*H];
__device__ float g_tmp[BS*H];
__device__ float g_hatt[BS*H];
__device__ float g_prex[BS*H];
__device__ float g_outs[BS*H];
__device__ float g_W2T[H*H];
__device__ float g_Wc[3*H*H];
__device__ float g_bc[3*H];
__device__ float g_z[B*H];
__device__ unsigned g_bar;

__global__ void init_kernel() { g_bar = 0u; }

// ---------------- generic fp32 GEMM: C[M,N] = A[M,K] * W[N,K]^T + bias ----------------
__global__ __launch_bounds__(256) void gemm_tn(
    const float* __restrict__ A, int lda,
    const float* __restrict__ W, int ldw,
    const float* __restrict__ bias,
    float* __restrict__ C,
    int M, int N, int K)
{
    __shared__ float As[16][64];
    __shared__ float Ws[16][64];
    int tid = threadIdx.x;
    int tx = tid & 15, ty = tid >> 4;
    int bm = blockIdx.y * 64, bn = blockIdx.x * 64;
    int lr = tid >> 2;
    int lk = (tid & 3) << 2;
    const float* Ap = A + (size_t)(bm + lr) * lda + lk;
    const float* Wp = W + (size_t)(bn + lr) * ldw + lk;
    float acc[4][4];
#pragma unroll
    for (int i = 0; i < 4; i++)
#pragma unroll
        for (int j = 0; j < 4; j++) acc[i][j] = 0.f;

    for (int k0 = 0; k0 < K; k0 += 16) {
        float4 av = *(const float4*)(Ap + k0);
        float4 wv = *(const float4*)(Wp + k0);
        __syncthreads();
        As[lk + 0][lr] = av.x; As[lk + 1][lr] = av.y; As[lk + 2][lr] = av.z; As[lk + 3][lr] = av.w;
        Ws[lk + 0][lr] = wv.x; Ws[lk + 1][lr] = wv.y; Ws[lk + 2][lr] = wv.z; Ws[lk + 3][lr] = wv.w;
        __syncthreads();
#pragma unroll
        for (int kk = 0; kk < 16; kk++) {
            float4 a = *(const float4*)&As[kk][ty << 2];
            float4 w = *(const float4*)&Ws[kk][tx << 2];
            float ar[4] = {a.x, a.y, a.z, a.w};
            float wr[4] = {w.x, w.y, w.z, w.w};
#pragma unroll
            for (int i = 0; i < 4; i++)
#pragma unroll
                for (int j = 0; j < 4; j++)
                    acc[i][j] += ar[i] * wr[j];
        }
    }
#pragma unroll
    for (int j = 0; j < 4; j++) {
        int n = bn + (tx << 2) + j;
        float bv = bias ? bias[n] : 0.f;
#pragma unroll
        for (int i = 0; i < 4; i++) {
            int m = bm + (ty << 2) + i;
            C[(size_t)m * N + n] = acc[i][j] + bv;
        }
    }
}

// ---------------- flash attention (fp32, no mask), 32-key tiles ----------------
__global__ __launch_bounds__(128) void attn_kernel(const float* __restrict__ qkv,
                                                   float* __restrict__ ctx)
{
    __shared__ float Ks[32][64];
    __shared__ float Vs[32][64];
    int qt = blockIdx.x;          // q tile (16)
    int bh = blockIdx.y;          // b*NH+h (64)
    int b = bh >> 3, h = bh & 7;
    const float* base = qkv + (size_t)b * S * 1536;
    int tid = threadIdx.x;
    int r = tid >> 1, half = tid & 1;   // 2 threads per q-row, split over HD
    int qrow = qt * 64 + r;

    float q[32];
    {
        const float* qp = base + (size_t)qrow * 1536 + h * 64 + half * 32;
#pragma unroll
        for (int i = 0; i < 32; i++) q[i] = qp[i] * 0.125f;   // 1/sqrt(64)
    }
    float m = -1e30f, l = 0.f;
    float acc[32];
#pragma unroll
    for (int i = 0; i < 32; i++) acc[i] = 0.f;

    for (int kt = 0; kt < 32; kt++) {
        __syncthreads();
#pragma unroll
        for (int ii = 0; ii < 4; ii++) {
            int fi = tid + 128 * ii;          // 0..511 float4s
            int row = fi >> 4;
            int d4 = (fi & 15) << 2;
            const float* kp = base + (size_t)(kt * 32 + row) * 1536 + 512 + h * 64 + d4;
            *(float4*)&Ks[row][d4] = *(const float4*)kp;
            *(float4*)&Vs[row][d4] = *(const float4*)(kp + 512);
        }
        __syncthreads();

        float s[32];
#pragma unroll
        for (int j = 0; j < 32; j++) {
            float a = 0.f;
#pragma unroll
            for (int i = 0; i < 32; i += 4) {
                float4 kk = *(const float4*)&Ks[j][half * 32 + i];
                a += q[i] * kk.x + q[i + 1] * kk.y + q[i + 2] * kk.z + q[i + 3] * kk.w;
            }
            s[j] = a;
        }
#pragma unroll
        for (int j = 0; j < 32; j++) s[j] += __shfl_xor_sync(0xffffffffu, s[j], 1);

        float mx = s[0];
#pragma unroll
        for (int j = 1; j < 32; j++) mx = fmaxf(mx, s[j]);
        float mnew = fmaxf(m, mx);
        float corr = __expf(m - mnew);
        l *= corr;
#pragma unroll
        for (int i = 0; i < 32; i++) acc[i] *= corr;
        float ls = 0.f;
#pragma unroll
        for (int j = 0; j < 32; j++) { float p = __expf(s[j] - mnew); s[j] = p; ls += p; }
        l += ls;
        m = mnew;
#pragma unroll
        for (int j = 0; j < 32; j++) {
#pragma unroll
            for (int i = 0; i < 32; i += 4) {
                float4 vv = *(const float4*)&Vs[j][half * 32 + i];
                acc[i]     += s[j] * vv.x;
                acc[i + 1] += s[j] * vv.y;
                acc[i + 2] += s[j] * vv.z;
                acc[i + 3] += s[j] * vv.w;
            }
        }
    }
    float inv = 1.f / l;
    float* op = ctx + ((size_t)b * S + qrow) * 512 + h * 64 + half * 32;
#pragma unroll
    for (int i = 0; i < 32; i++) op[i] = acc[i] * inv;
}

// ---------------- fused residual + LayerNorm ----------------
__global__ __launch_bounds__(128) void ln_kernel(
    const float* __restrict__ A, const float* __restrict__ Bres,
    const float* __restrict__ gma, const float* __restrict__ bta,
    float* __restrict__ out)
{
    int row = blockIdx.x, tid = threadIdx.x;
    const float4* a4 = (const float4*)(A + (size_t)row * 512);
    const float4* b4 = (const float4*)(Bres + (size_t)row * 512);
    float4 x = a4[tid], y = b4[tid];
    float4 v = make_float4(x.x + y.x, x.y + y.y, x.z + y.z, x.w + y.w);
    float s = v.x + v.y + v.z + v.w;
    float q = v.x * v.x + v.y * v.y + v.z * v.z + v.w * v.w;
#pragma unroll
    for (int o = 16; o > 0; o >>= 1) {
        s += __shfl_down_sync(0xffffffffu, s, o);
        q += __shfl_down_sync(0xffffffffu, q, o);
    }
    __shared__ float rs[4], rq[4];
    int wid = tid >> 5;
    if ((tid & 31) == 0) { rs[wid] = s; rq[wid] = q; }
    __syncthreads();
    float ts = rs[0] + rs[1] + rs[2] + rs[3];
    float tq = rq[0] + rq[1] + rq[2] + rq[3];
    float mean = ts * (1.f / 512.f);
    float var = tq * (1.f / 512.f) - mean * mean;
    float rstd = rsqrtf(var + 1e-5f);
    float4 gg = ((const float4*)gma)[tid];
    float4 bb = ((const float4*)bta)[tid];
    float4 o;
    o.x = (v.x - mean) * rstd * gg.x + bb.x;
    o.y = (v.y - mean) * rstd * gg.y + bb.y;
    o.z = (v.z - mean) * rstd * gg.z + bb.z;
    o.w = (v.w - mean) * rstd * gg.w + bb.w;
    ((float4*)(out + (size_t)row * 512))[tid] = o;
}

// ---------------- 512x512 transpose ----------------
__global__ void transpose_kernel(const float* __restrict__ in, float* __restrict__ out)
{
    __shared__ float tile[32][33];
    int bx = blockIdx.x * 32, by = blockIdx.y * 32;
    int tx = threadIdx.x, ty = threadIdx.y;  // (32, 8)
    for (int i = 0; i < 32; i += 8)
        tile[ty + i][tx] = in[(size_t)(by + ty + i) * 512 + bx + tx];
    __syncthreads();
    for (int i = 0; i < 32; i += 8)
        out[(size_t)(bx + ty + i) * 512 + by + tx] = tile[tx][ty + i];
}

// ---------------- bc = Wfgh @ b2 + b_fgh ----------------
__global__ void bc_kernel(const float* __restrict__ tw, const float* __restrict__ gw,
                          const float* __restrict__ hw, const float* __restrict__ tb,
                          const float* __restrict__ gb, const float* __restrict__ hb,
                          const float* __restrict__ b2)
{
    int i = blockIdx.x * blockDim.x + threadIdx.x;
    if (i >= 1536) return;
    int part = i >> 9, r = i & 511;
    const float* Wr; float bv;
    if (part == 0)      { Wr = tw + (size_t)r * 512; bv = tb[r]; }
    else if (part == 1) { Wr = gw + (size_t)r * 512; bv = gb[r]; }
    else                { Wr = hw + (size_t)r * 512; bv = hb[r]; }
    float s = bv;
    for (int j = 0; j < 512; j++) s += Wr[j] * b2[j];
    g_bc[i] = s;
}

// ---------------- persistent LTC scan ----------------
#define NBLK 128

__device__ __forceinline__ void bar_arrive_wait(unsigned target)
{
    __syncthreads();
    if (threadIdx.x == 0) {
        unsigned* p = &g_bar;
        asm volatile("red.release.gpu.global.add.u32 [%0], %1;" :: "l"(p), "r"(1u) : "memory");
        unsigned v;
        do {
            asm volatile("ld.acquire.gpu.global.u32 %0, [%1];" : "=r"(v) : "l"(p) : "memory");
        } while (v < target);
    }
    __syncthreads();
}

// 128 CTAs x 128 threads. CTA owns 4 hidden columns. Warp w (0..3) handles
// batches {w, w+4}: lanes [0,16) -> batch w, lanes [16,32) -> batch w+4.
// Within each 16-lane half, lane owns k-offsets (lane&15)*4 + 64*i (conflict-free
// float4 LDS: 16 distinct float4s + half-broadcast per instruction).
__global__ __launch_bounds__(128) void scan_kernel(const float* __restrict__ ltc_w1)
{
    __shared__ float sW1[4][512];    // 4 z-columns of W1h (state half of ltc_w1)
    __shared__ float sWc[12][512];   // 12 fgh rows of merged Wc
    __shared__ float sbc[12];
    int blk = blockIdx.x, tid = threadIdx.x;

#pragma unroll
    for (int r = 0; r < 4; r++)
        for (int k = tid; k < 512; k += 128)
            sW1[r][k] = ltc_w1[(size_t)(4 * blk + r) * 1024 + 512 + k];
#pragma unroll
    for (int r = 0; r < 12; r++) {
        int row = (r >> 2) * 512 + 4 * blk + (r & 3);
        for (int k = tid; k < 512; k += 128)
            sWc[r][k] = g_Wc[(size_t)row * 512 + k];
    }
    if (tid < 12) sbc[tid] = g_bc[(tid >> 2) * 512 + 4 * blk + (tid & 3)];
    __syncthreads();

    int w = tid >> 5;
    int lane = tid & 31;
    int half = lane >> 4;
    int c16 = lane & 15;
    int l4 = c16 * 4;
    int batch = w + 4 * half;
    unsigned nb = 0;

    for (int t = 0; t < S; t++) {
        // ---- stage 1: z = tanh(prex[t] + state @ W1h^T) ----
        float a0 = 0.f, a1 = 0.f, a2 = 0.f, a3 = 0.f;
        if (t > 0) {
            const float* st = g_outs + ((size_t)batch * S + (t - 1)) * H;
#pragma unroll
            for (int i = 0; i < 8; i++) {
                int k = l4 + 64 * i;
                float4 s4 = __ldcg((const float4*)(st + k));
                float4 w0 = *(const float4*)&sW1[0][k];
                float4 w1v = *(const float4*)&sW1[1][k];
                float4 w2v = *(const float4*)&sW1[2][k];
                float4 w3v = *(const float4*)&sW1[3][k];
                a0 += s4.x * w0.x + s4.y * w0.y + s4.z * w0.z + s4.w * w0.w;
                a1 += s4.x * w1v.x + s4.y * w1v.y + s4.z * w1v.z + s4.w * w1v.w;
                a2 += s4.x * w2v.x + s4.y * w2v.y + s4.z * w2v.z + s4.w * w2v.w;
                a3 += s4.x * w3v.x + s4.y * w3v.y + s4.z * w3v.z + s4.w * w3v.w;
            }
#pragma unroll
            for (int o = 1; o <= 8; o <<= 1) {
                a0 += __shfl_xor_sync(0xffffffffu, a0, o);
                a1 += __shfl_xor_sync(0xffffffffu, a1, o);
                a2 += __shfl_xor_sync(0xffffffffu, a2, o);
                a3 += __shfl_xor_sync(0xffffffffu, a3, o);
            }
        }
        if (c16 < 4) {
            float a = (c16 == 0) ? a0 : (c16 == 1) ? a1 : (c16 == 2) ? a2 : a3;
            float z = tanhf(g_prex[((size_t)batch * S + t) * H + 4 * blk + c16] + a);
            g_z[batch * H + 4 * blk + c16] = z;
        }
        bar_arrive_wait(++nb * NBLK);

        // ---- stage 2: fgh = z @ Wc^T + bc ; state update ----
        float acc[12];
#pragma unroll
        for (int r = 0; r < 12; r++) acc[r] = 0.f;
        const float* zp = g_z + batch * H;
#pragma unroll
        for (int i = 0; i < 8; i++) {
            int k = l4 + 64 * i;
            float4 z4 = __ldcg((const float4*)(zp + k));
#pragma unroll
            for (int r = 0; r < 12; r++) {
                float4 wv = *(const float4*)&sWc[r][k];
                acc[r] += z4.x * wv.x + z4.y * wv.y + z4.z * wv.z + z4.w * wv.w;
            }
        }
#pragma unroll
        for (int r = 0; r < 12; r++) {
#pragma unroll
            for (int o = 1; o <= 8; o <<= 1)
                acc[r] += __shfl_xor_sync(0xffffffffu, acc[r], o);
            acc[r] += sbc[r];
        }
        if (c16 < 4) {
            float fv = (c16 == 0) ? acc[0] : (c16 == 1) ? acc[1] : (c16 == 2) ? acc[2] : acc[3];
            float gv = (c16 == 0) ? acc[4] : (c16 == 1) ? acc[5] : (c16 == 2) ? acc[6] : acc[7];
            float hv = (c16 == 0) ? acc[8] : (c16 == 1) ? acc[9] : (c16 == 2) ? acc[10] : acc[11];
            float ft = 1.f / (1.f + __expf(-fv));              // sigmoid(f)
            float gate = 1.f / (1.f + __expf(ft * (float)t));  // sigmoid(-ft * t)
            float sv = gate * gv + (1.f - gate) * hv;
            g_outs[((size_t)batch * S + t) * H + 4 * blk + c16] = sv;
        }
        bar_arrive_wait(++nb * NBLK);
    }
}

// ---------------- host launch ----------------
extern "C" void kernel_launch(void* const* d_in, const int* in_sizes, int n_in,
                              void* d_out, int out_size)
{
    const float* x    = (const float*)d_in[0];
    const float* ipw  = (const float*)d_in[1];
    const float* ipb  = (const float*)d_in[2];
    const float* qkvw = (const float*)d_in[3];
    const float* qkvb = (const float*)d_in[4];
    const float* aow  = (const float*)d_in[5];
    const float* aob  = (const float*)d_in[6];
    const float* w1   = (const float*)d_in[7];
    const float* b1   = (const float*)d_in[8];
    const float* w2   = (const float*)d_in[9];
    const float* b2   = (const float*)d_in[10];
    const float* tw   = (const float*)d_in[11];
    const float* tb   = (const float*)d_in[12];
    const float* gw   = (const float*)d_in[13];
    const float* gb   = (const float*)d_in[14];
    const float* hw   = (const float*)d_in[15];
    const float* hb   = (const float*)d_in[16];
    const float* n1g  = (const float*)d_in[17];
    const float* n1b  = (const float*)d_in[18];
    const float* n2g  = (const float*)d_in[19];
    const float* n2b  = (const float*)d_in[20];
    const float* ow   = (const float*)d_in[21];
    const float* ob   = (const float*)d_in[22];
    float* out = (float*)d_out;

    float *ph, *pqkv, *pctx, *ptmp, *phatt, *pprex, *pouts, *pW2T, *pWc;
    cudaGetSymbolAddress((void**)&ph,    g_h);
    cudaGetSymbolAddress((void**)&pqkv,  g_qkv);
    cudaGetSymbolAddress((void**)&pctx,  g_ctx);
    cudaGetSymbolAddress((void**)&ptmp,  g_tmp);
    cudaGetSymbolAddress((void**)&phatt, g_hatt);
    cudaGetSymbolAddress((void**)&pprex, g_prex);
    cudaGetSymbolAddress((void**)&pouts, g_outs);
    cudaGetSymbolAddress((void**)&pW2T,  g_W2T);
    cudaGetSymbolAddress((void**)&pWc,   g_Wc);

    init_kernel<<<1, 1>>>();

    // h = x @ in_proj_w^T + b
    gemm_tn<<<dim3(8, 128), 256>>>(x, 512, ipw, 512, ipb, ph, 8192, 512, 512);
    // qkv = h @ qkv_w^T + b
    gemm_tn<<<dim3(24, 128), 256>>>(ph, 512, qkvw, 512, qkvb, pqkv, 8192, 1536, 512);
    // attention
    attn_kernel<<<dim3(16, 64), 128>>>(pqkv, pctx);
    // attn out proj
    gemm_tn<<<dim3(8, 128), 256>>>(pctx, 512, aow, 512, aob, ptmp, 8192, 512, 512);
    // h_att = LN(h + attn_out)
    ln_kernel<<<8192, 128>>>(ph, ptmp, n1g, n1b, phatt);
    // prex = h_att @ W1x^T + b1  (x-half of ltc_w1, ldw = 1024)
    gemm_tn<<<dim3(8, 128), 256>>>(phatt, 512, w1, 1024, b1, pprex, 8192, 512, 512);
    // W2T, then Wc = [tw;gw;hw] @ W2   (as A @ (W2^T)^T)
    transpose_kernel<<<dim3(16, 16), dim3(32, 8)>>>(w2, pW2T);
    gemm_tn<<<dim3(8, 8), 256>>>(tw, 512, pW2T, 512, nullptr, pWc,            512, 512, 512);
    gemm_tn<<<dim3(8, 8), 256>>>(gw, 512, pW2T, 512, nullptr, pWc + 262144,   512, 512, 512);
    gemm_tn<<<dim3(8, 8), 256>>>(hw, 512, pW2T, 512, nullptr, pWc + 524288,   512, 512, 512);
    bc_kernel<<<6, 256>>>(tw, gw, hw, tb, gb, hb, b2);
    // persistent scan
    scan_kernel<<<NBLK, 128>>>(w1);
    // LN2 + out proj
    ln_kernel<<<8192, 128>>>(pouts, phatt, n2g, n2b, ptmp);
    gemm_tn<<<dim3(8, 128), 256>>>(ptmp, 512, ow, 512, ob, out, 8192, 512, 512);
}